// round 15
// baseline (speedup 1.0000x reference)
#include <cuda_runtime.h>
#include <cuda_fp16.h>

// Sinkhorn distance, B=4, N=4096, d=64, EPS=1e-3, 100 iterations, STAB=1e-8.
//   1) softmax rows + ||.||^2
//   2) row-max m_i of arg_ij = min((2*dot - x2_i - y2_j)/eps, 0)
//   3) build K~ = exp(arg - m_i) fp16, row-major ONLY (no transpose)
//   4) 100x fused pass: ONE read of K~ per iteration computes BOTH
//        u~_i = e^m/(e^m * (K~ v) + stab)   and   w_j += u~_i * K~_ij
//      512 thr/block, occupancy 1 (128-reg budget -> no spill), 4-deep
//      register pipeline (3 loads in flight), ONE barrier per round
//      (fold of round i-1 deferred into round i). Cross-block w via
//      atomicAdd into per-iteration pre-zeroed buffers.
//      First 109MB of K~ loaded evict_last (L2-pinned across iterations),
//      rest evict_first.
//   5) dist = sum u~_i * exp(arg_ij - m_i) * v_j * cost_ij
// All scratch in __device__ globals. Graph-capturable, allocation-free.

#define BATCH 4
#define NN 4096
#define DD 64
#define INV_EPS 1000.0f
#define MAX_ITER 100
#define STAB 1e-8f
#define TI 64
#define TJ 64
#define NBLK_PER_B 37          // 4 * 37 = 148 blocks = 1 per SM
#define ROWS_PIN 3328          // rows/batch kept L2-resident (4*3328*8KB = 109MB)

static constexpr size_t KELEMS = (size_t)BATCH * NN * NN;

__device__ float g_xf[BATCH * NN * DD];
__device__ float g_yf[BATCH * NN * DD];
__device__ float g_x2[BATCH * NN];
__device__ float g_y2[BATCH * NN];
__device__ float g_m[BATCH * NN];
__device__ __align__(128) __half g_K[KELEMS];        // K~ row-major [b][i][j]
__device__ float g_wv[(MAX_ITER + 1) * BATCH * NN];  // w sums; v = 1/(w+stab)
__device__ float g_ut[BATCH * NN];                   // u~ = u * exp(m)
__device__ float g_part[BATCH * 64 * 64];

// ---------------------------------------------------------------------------
// 1) softmax over last dim (64) + sum of squares. One warp per row.
// ---------------------------------------------------------------------------
__global__ void softmax_kernel(const float* __restrict__ x, const float* __restrict__ y) {
    int row  = blockIdx.x * 8 + (threadIdx.x >> 5);
    int lane = threadIdx.x & 31;
    const float* src;
    float* dst;
    float* s2out;
    int r;
    if (row < BATCH * NN) { src = x; dst = g_xf; s2out = g_x2; r = row; }
    else                  { src = y; dst = g_yf; s2out = g_y2; r = row - BATCH * NN; }
    const float* p = src + (size_t)r * DD;
    float a0 = p[lane], a1 = p[lane + 32];
    float mx = fmaxf(a0, a1);
#pragma unroll
    for (int o = 16; o > 0; o >>= 1) mx = fmaxf(mx, __shfl_xor_sync(0xffffffffu, mx, o));
    float e0 = expf(a0 - mx), e1 = expf(a1 - mx);
    float s = e0 + e1;
#pragma unroll
    for (int o = 16; o > 0; o >>= 1) s += __shfl_xor_sync(0xffffffffu, s, o);
    float p0 = e0 / s, p1 = e1 / s;
    dst[(size_t)r * DD + lane]      = p0;
    dst[(size_t)r * DD + lane + 32] = p1;
    float q = p0 * p0 + p1 * p1;
#pragma unroll
    for (int o = 16; o > 0; o >>= 1) q += __shfl_xor_sync(0xffffffffu, q, o);
    if (lane == 0) s2out[r] = q;
}

// ---------------------------------------------------------------------------
// 2) row max of arg over all j. grid = B * (N/64) = 256 blocks, 256 threads.
// ---------------------------------------------------------------------------
__global__ void rowmax_kernel() {
    int b  = blockIdx.x >> 6;
    int ib = (blockIdx.x & 63) << 6;
    __shared__ float xs[TI][DD];
    __shared__ float ys[TJ][DD + 1];
    __shared__ float x2s[TI], y2s[TJ];
    __shared__ float red[TI][17];
    int tid = threadIdx.x;
    for (int t = tid; t < TI * DD; t += 256)
        xs[t >> 6][t & 63] = g_xf[(size_t)(b * NN + ib + (t >> 6)) * DD + (t & 63)];
    if (tid < TI) x2s[tid] = g_x2[b * NN + ib + tid];
    int ty = tid >> 4, tx = tid & 15;
    float mymax[4] = {-1e30f, -1e30f, -1e30f, -1e30f};
    for (int jb = 0; jb < NN; jb += TJ) {
        __syncthreads();
        for (int t = tid; t < TJ * DD; t += 256)
            ys[t >> 6][t & 63] = g_yf[(size_t)(b * NN + jb + (t >> 6)) * DD + (t & 63)];
        if (tid < TJ) y2s[tid] = g_y2[b * NN + jb + tid];
        __syncthreads();
        float acc[4][4] = {};
#pragma unroll 16
        for (int k = 0; k < DD; ++k) {
            float a[4], bb[4];
#pragma unroll
            for (int r = 0; r < 4; ++r) a[r] = xs[ty * 4 + r][k];
#pragma unroll
            for (int c = 0; c < 4; ++c) bb[c] = ys[tx * 4 + c][k];
#pragma unroll
            for (int r = 0; r < 4; ++r)
#pragma unroll
                for (int c = 0; c < 4; ++c) acc[r][c] = fmaf(a[r], bb[c], acc[r][c]);
        }
#pragma unroll
        for (int r = 0; r < 4; ++r) {
            float x2 = x2s[ty * 4 + r];
#pragma unroll
            for (int c = 0; c < 4; ++c) {
                float arg = fminf((2.0f * acc[r][c] - x2 - y2s[tx * 4 + c]) * INV_EPS, 0.0f);
                mymax[r] = fmaxf(mymax[r], arg);
            }
        }
    }
    __syncthreads();
#pragma unroll
    for (int r = 0; r < 4; ++r) red[ty * 4 + r][tx] = mymax[r];
    __syncthreads();
    if (tid < TI) {
        float m = -1e30f;
#pragma unroll
        for (int t = 0; t < 16; ++t) m = fmaxf(m, red[tid][t]);
        g_m[b * NN + ib + tid] = m;
    }
}

// ---------------------------------------------------------------------------
// 3) build K~ fp16 (row-major only). grid = B * 64 * 64 = 16384 blocks.
// ---------------------------------------------------------------------------
__global__ void build_kernel() {
    int b   = blockIdx.x >> 12;
    int rem = blockIdx.x & 4095;
    int ib  = (rem >> 6) << 6;
    int jb  = (rem & 63) << 6;
    __shared__ float xs[TI][DD];
    __shared__ float ys[TJ][DD + 1];
    __shared__ float x2s[TI], y2s[TJ], ms[TI];
    int tid = threadIdx.x;
    for (int t = tid; t < TI * DD; t += 256)
        xs[t >> 6][t & 63] = g_xf[(size_t)(b * NN + ib + (t >> 6)) * DD + (t & 63)];
    for (int t = tid; t < TJ * DD; t += 256)
        ys[t >> 6][t & 63] = g_yf[(size_t)(b * NN + jb + (t >> 6)) * DD + (t & 63)];
    if (tid < TI) { x2s[tid] = g_x2[b * NN + ib + tid]; ms[tid] = g_m[b * NN + ib + tid]; }
    if (tid >= 64 && tid < 64 + TJ) y2s[tid - 64] = g_y2[b * NN + jb + tid - 64];
    __syncthreads();
    int ty = tid >> 4, tx = tid & 15;
    float acc[4][4] = {};
#pragma unroll 16
    for (int k = 0; k < DD; ++k) {
        float a[4], bb[4];
#pragma unroll
        for (int r = 0; r < 4; ++r) a[r] = xs[ty * 4 + r][k];
#pragma unroll
        for (int c = 0; c < 4; ++c) bb[c] = ys[tx * 4 + c][k];
#pragma unroll
        for (int r = 0; r < 4; ++r)
#pragma unroll
            for (int c = 0; c < 4; ++c) acc[r][c] = fmaf(a[r], bb[c], acc[r][c]);
    }
#pragma unroll
    for (int r = 0; r < 4; ++r) {
        int i = ty * 4 + r;
        float x2 = x2s[i];
        float m  = ms[i];
        __half hv[4];
#pragma unroll
        for (int c = 0; c < 4; ++c) {
            int j = tx * 4 + c;
            float arg = fminf((2.0f * acc[r][c] - x2 - y2s[j]) * INV_EPS, 0.0f);
            float kv  = __expf(arg - m);
            hv[c] = __float2half_rn(kv);
        }
        size_t rowo = (size_t)(b * NN + ib + i) * NN + jb + tx * 4;
        __half2* dst = reinterpret_cast<__half2*>(&g_K[rowo]);
        dst[0] = __halves2half2(hv[0], hv[1]);
        dst[1] = __halves2half2(hv[2], hv[3]);
    }
}

// ---------------------------------------------------------------------------
// init: wv[0] = N (so v0 = 1/(N+stab) ~= 1/N), wv[1..MAX_ITER] = 0
// ---------------------------------------------------------------------------
__global__ void init_wv_kernel() {
    int i = blockIdx.x * 256 + threadIdx.x;
    const int total = (MAX_ITER + 1) * BATCH * NN;
    if (i < total) g_wv[i] = (i < BATCH * NN) ? (float)NN : 0.0f;
}

// ---------------------------------------------------------------------------
// hinted 32-byte loads (sm_103 ptxas: evict hints require .v4.b64)
// ---------------------------------------------------------------------------
__device__ __forceinline__ ulonglong4 ldg32_pin(const void* p) {
    ulonglong4 r;
    asm("ld.global.L2::evict_last.v4.b64 {%0,%1,%2,%3}, [%4];"
        : "=l"(r.x), "=l"(r.y), "=l"(r.z), "=l"(r.w) : "l"(p));
    return r;
}
__device__ __forceinline__ ulonglong4 ldg32_stream(const void* p) {
    ulonglong4 r;
    asm("ld.global.L2::evict_first.v4.b64 {%0,%1,%2,%3}, [%4];"
        : "=l"(r.x), "=l"(r.y), "=l"(r.z), "=l"(r.w) : "l"(p));
    return r;
}

// ---------------------------------------------------------------------------
// 4) fused Sinkhorn iteration. grid = 148 blocks (1/SM), 512 threads =
//    16 warps = 2 row-groups x 8 column-stripes; lane owns 16 columns
//    (one 32B hinted load per row). Round i: dot(rows 2i,2i+1) -> barrier ->
//    {u for round i; fold round i-1}; prefetch 3 rounds ahead (kb[4]).
//    One barrier per round; 128-reg budget (occupancy 1) -> no spill.
// ---------------------------------------------------------------------------
__global__ void __launch_bounds__(512, 1) fused_iter_kernel(int t) {
    const float* __restrict__ wvp = g_wv + (size_t)t * (BATCH * NN);
    float* __restrict__ wvn = g_wv + (size_t)(t + 1) * (BATCH * NN);
    int b   = blockIdx.x & 3;
    int blk = blockIdx.x >> 2;
    int start = (blk * NN) / NBLK_PER_B;
    int end   = ((blk + 1) * NN) / NBLK_PER_B;
    int nrows = end - start;
    int tid = threadIdx.x;
    int w = tid >> 5, l = tid & 31;
    int g = w >> 3;          // row group 0/1
    int s = w & 7;           // column stripe
    int c0 = s * 512 + l * 16;

    __shared__ float spart[2][16];
    __shared__ float sus[2][2];
    __shared__ float ms[120];
    for (int r = tid; r < nrows; r += 512) ms[r] = g_m[b * NN + start + r];

    float v[16], wa[16];
#pragma unroll
    for (int k = 0; k < 16; ++k) {
        v[k]  = 1.0f / (wvp[b * NN + c0 + k] + STAB);
        wa[k] = 0.0f;
    }

    const __half* Kb = g_K + (size_t)b * NN * NN + c0;

    ulonglong4 kb[4];
#pragma unroll
    for (int q = 0; q < 4; ++q) kb[q] = make_ulonglong4(0, 0, 0, 0);

    __syncthreads();  // ms ready

    // prefetch rounds 0..2 into slots 0..2 (group g's row in round r is 2r+g)
#pragma unroll
    for (int r = 0; r < 3; ++r) {
        int lr = 2 * r + g;
        if (lr < nrows) {
            int row = start + lr;
            const void* p = (const void*)(Kb + (size_t)row * NN);
            kb[r] = (row < ROWS_PIN) ? ldg32_pin(p) : ldg32_stream(p);
        }
    }

    int nrounds = (nrows + 1) >> 1;
    for (int i = 0; i < nrounds; ++i) {
        int slot = i & 3;
        int par  = i & 1;
        int lr   = 2 * i + g;

        // partial dot over this lane's 16 columns + intra-warp reduce
        {
            float p = 0.0f;
            if (lr < nrows) {   // warp-uniform (depends only on g, i)
                const __half2* h = (const __half2*)&kb[slot];
#pragma unroll
                for (int k = 0; k < 8; ++k) {
                    float2 f = __half22float2(h[k]);
                    p = fmaf(f.x, v[2 * k], fmaf(f.y, v[2 * k + 1], p));
                }
            }
#pragma unroll
            for (int o = 16; o > 0; o >>= 1) p += __shfl_xor_sync(0xffffffffu, p, o);
            if (l == 0) spart[par][w] = p;
        }
        __syncthreads();

        // warps 0,1: cross-stripe reduce + u for this round's rows
        if (w < 2) {
            float p = (l < 8) ? spart[par][w * 8 + l] : 0.0f;
#pragma unroll
            for (int o = 16; o > 0; o >>= 1) p += __shfl_xor_sync(0xffffffffu, p, o);
            if (l == 0) {
                int r2 = 2 * i + w;
                if (r2 < nrows) {
                    float m  = ms[r2];
                    float em = expf(m);
                    float u  = em / (em * p + STAB);   // u~ = u * e^m
                    sus[par][w] = u;
                    g_ut[b * NN + start + r2] = u;
                }
            }
        }

        // fold PREVIOUS round's row (u from last round's post-barrier write)
        if (i > 0) {
            int lp = 2 * (i - 1) + g;
            if (lp < nrows) {
                float u = sus[par ^ 1][g];
                const __half2* h = (const __half2*)&kb[(i - 1) & 3];
#pragma unroll
                for (int k = 0; k < 8; ++k) {
                    float2 f = __half22float2(h[k]);
                    wa[2 * k]     = fmaf(u, f.x, wa[2 * k]);
                    wa[2 * k + 1] = fmaf(u, f.y, wa[2 * k + 1]);
                }
            }
        }

        // prefetch round i+3 into slot (i+3)&3 == (i-1)&3 (fold above is done)
        {
            int lf = 2 * (i + 3) + g;
            if (lf < nrows) {
                int row = start + lf;
                const void* p = (const void*)(Kb + (size_t)row * NN);
                kb[(i + 3) & 3] = (row < ROWS_PIN) ? ldg32_pin(p) : ldg32_stream(p);
            }
        }
    }

    // epilogue: fold the last round's rows
    __syncthreads();
    {
        int i  = nrounds - 1;
        int lp = 2 * i + g;
        if (lp < nrows) {
            float u = sus[i & 1][g];
            const __half2* h = (const __half2*)&kb[i & 3];
#pragma unroll
            for (int k = 0; k < 8; ++k) {
                float2 f = __half22float2(h[k]);
                wa[2 * k]     = fmaf(u, f.x, wa[2 * k]);
                wa[2 * k + 1] = fmaf(u, f.y, wa[2 * k + 1]);
            }
        }
    }

#pragma unroll
    for (int k = 0; k < 16; ++k)
        atomicAdd(&wvn[b * NN + c0 + k], wa[k]);
}

// ---------------------------------------------------------------------------
// 5) dist partials: sum_ij u~_i * exp(arg_ij - m_i) * v_j * cost_ij
//    v_j = 1/(wv[MAX_ITER][j] + stab)
// ---------------------------------------------------------------------------
__global__ void final_kernel() {
    int b   = blockIdx.x >> 12;
    int rem = blockIdx.x & 4095;
    int ib  = (rem >> 6) << 6;
    int jb  = (rem & 63) << 6;
    __shared__ float xs[TI][DD];
    __shared__ float ys[TJ][DD + 1];
    __shared__ float x2s[TI], y2s[TJ], ms[TI], uts[TI], vs[TJ];
    __shared__ float redsum[256];
    int tid = threadIdx.x;
    for (int t = tid; t < TI * DD; t += 256)
        xs[t >> 6][t & 63] = g_xf[(size_t)(b * NN + ib + (t >> 6)) * DD + (t & 63)];
    for (int t = tid; t < TJ * DD; t += 256)
        ys[t >> 6][t & 63] = g_yf[(size_t)(b * NN + jb + (t >> 6)) * DD + (t & 63)];
    if (tid < TI) {
        x2s[tid] = g_x2[b * NN + ib + tid];
        ms[tid]  = g_m[b * NN + ib + tid];
        uts[tid] = g_ut[b * NN + ib + tid];
    }
    if (tid >= 64 && tid < 64 + TJ) {
        y2s[tid - 64] = g_y2[b * NN + jb + tid - 64];
        vs[tid - 64]  = 1.0f / (g_wv[(size_t)MAX_ITER * (BATCH * NN) + b * NN + jb + tid - 64] + STAB);
    }
    __syncthreads();
    int ty = tid >> 4, tx = tid & 15;
    float acc[4][4] = {};
#pragma unroll 16
    for (int k = 0; k < DD; ++k) {
        float a[4], bb[4];
#pragma unroll
        for (int r = 0; r < 4; ++r) a[r] = xs[ty * 4 + r][k];
#pragma unroll
        for (int c = 0; c < 4; ++c) bb[c] = ys[tx * 4 + c][k];
#pragma unroll
        for (int r = 0; r < 4; ++r)
#pragma unroll
            for (int c = 0; c < 4; ++c) acc[r][c] = fmaf(a[r], bb[c], acc[r][c]);
    }
    float tsum = 0.0f;
#pragma unroll
    for (int r = 0; r < 4; ++r) {
        int i = ty * 4 + r;
        float x2 = x2s[i], m = ms[i], ut = uts[i];
#pragma unroll
        for (int c = 0; c < 4; ++c) {
            int j = tx * 4 + c;
            float cost = fmaxf(x2 + y2s[j] - 2.0f * acc[r][c], 0.0f);
            float kk   = __expf(-cost * INV_EPS - m);
            tsum = fmaf(ut * kk, vs[j] * cost, tsum);
        }
    }
    redsum[tid] = tsum;
    __syncthreads();
#pragma unroll
    for (int o = 128; o > 0; o >>= 1) {
        if (tid < o) redsum[tid] += redsum[tid + o];
        __syncthreads();
    }
    if (tid == 0) g_part[blockIdx.x] = redsum[0];
}

__global__ void reduce_kernel(float* __restrict__ out) {
    __shared__ float sh[256];
    float s = 0.0f;
    for (int t = threadIdx.x; t < BATCH * 64 * 64; t += 256) s += g_part[t];
    sh[threadIdx.x] = s;
    __syncthreads();
#pragma unroll
    for (int o = 128; o > 0; o >>= 1) {
        if (threadIdx.x < o) sh[threadIdx.x] += sh[threadIdx.x + o];
        __syncthreads();
    }
    if (threadIdx.x == 0) out[0] = sh[0];
}

extern "C" void kernel_launch(void* const* d_in, const int* in_sizes, int n_in,
                              void* d_out, int out_size) {
    const float* x = (const float*)d_in[0];
    const float* y = (const float*)d_in[1];
    float* out = (float*)d_out;

    softmax_kernel<<<(2 * BATCH * NN) / 8, 256>>>(x, y);
    rowmax_kernel<<<BATCH * (NN / 64), 256>>>();
    build_kernel<<<BATCH * 64 * 64, 256>>>();
    {
        const int total = (MAX_ITER + 1) * BATCH * NN;
        init_wv_kernel<<<(total + 255) / 256, 256>>>();
    }
    for (int it = 0; it < MAX_ITER; ++it) {
        fused_iter_kernel<<<4 * NBLK_PER_B, 512>>>(it);
    }
    final_kernel<<<BATCH * 64 * 64, 256>>>();
    reduce_kernel<<<1, 256>>>(out);
}

// round 16
// speedup vs baseline: 1.3202x; 1.3202x over previous
#include <cuda_runtime.h>
#include <cuda_fp16.h>

// Sinkhorn distance, B=4, N=4096, d=64, EPS=1e-3, 100 iterations, STAB=1e-8.
//   1) softmax rows + ||.||^2
//   2) row-max m_i of arg_ij = min((2*dot - x2_i - y2_j)/eps, 0)
//   3) build K~ = exp(arg - m_i) fp16, row-major ONLY
//   4) 100x one-pass iteration kernel (134MB/iter):
//      groups of 32 rows: phase1 = each warp computes ONE full-row dot
//      (v in smem) -> u;  phase2 = each warp folds the 32 rows over its
//      private 128-column stripe into registers (stripe re-reads are L1/L2
//      hits). 8 barriers/iter. Cross-block w via atomicAdd into
//      per-iteration pre-zeroed buffers; v_j = 1/(w_j+stab) next launch.
//      First 109MB of K~ loaded evict_last (L2-pinned), rest evict_first.
//   5) dist = sum u~_i * exp(arg_ij - m_i) * v_j * cost_ij
// All scratch in __device__ globals. Graph-capturable, allocation-free.

#define BATCH 4
#define NN 4096
#define DD 64
#define INV_EPS 1000.0f
#define MAX_ITER 100
#define STAB 1e-8f
#define TI 64
#define TJ 64
#define NBLK_PER_B 37          // 4 * 37 = 148 blocks = 1 per SM
#define ROWS_PIN 3328          // rows/batch kept L2-resident (4*3328*8KB = 109MB)

static constexpr size_t KELEMS = (size_t)BATCH * NN * NN;

__device__ float g_xf[BATCH * NN * DD];
__device__ float g_yf[BATCH * NN * DD];
__device__ float g_x2[BATCH * NN];
__device__ float g_y2[BATCH * NN];
__device__ float g_m[BATCH * NN];
__device__ __align__(128) __half g_K[KELEMS];        // K~ row-major [b][i][j]
__device__ float g_wv[(MAX_ITER + 1) * BATCH * NN];  // w sums; v = 1/(w+stab)
__device__ float g_ut[BATCH * NN];                   // u~ = u * exp(m)
__device__ float g_part[BATCH * 64 * 64];

// ---------------------------------------------------------------------------
// 1) softmax over last dim (64) + sum of squares. One warp per row.
// ---------------------------------------------------------------------------
__global__ void softmax_kernel(const float* __restrict__ x, const float* __restrict__ y) {
    int row  = blockIdx.x * 8 + (threadIdx.x >> 5);
    int lane = threadIdx.x & 31;
    const float* src;
    float* dst;
    float* s2out;
    int r;
    if (row < BATCH * NN) { src = x; dst = g_xf; s2out = g_x2; r = row; }
    else                  { src = y; dst = g_yf; s2out = g_y2; r = row - BATCH * NN; }
    const float* p = src + (size_t)r * DD;
    float a0 = p[lane], a1 = p[lane + 32];
    float mx = fmaxf(a0, a1);
#pragma unroll
    for (int o = 16; o > 0; o >>= 1) mx = fmaxf(mx, __shfl_xor_sync(0xffffffffu, mx, o));
    float e0 = expf(a0 - mx), e1 = expf(a1 - mx);
    float s = e0 + e1;
#pragma unroll
    for (int o = 16; o > 0; o >>= 1) s += __shfl_xor_sync(0xffffffffu, s, o);
    float p0 = e0 / s, p1 = e1 / s;
    dst[(size_t)r * DD + lane]      = p0;
    dst[(size_t)r * DD + lane + 32] = p1;
    float q = p0 * p0 + p1 * p1;
#pragma unroll
    for (int o = 16; o > 0; o >>= 1) q += __shfl_xor_sync(0xffffffffu, q, o);
    if (lane == 0) s2out[r] = q;
}

// ---------------------------------------------------------------------------
// 2) row max of arg over all j. grid = B * (N/64) = 256 blocks, 256 threads.
// ---------------------------------------------------------------------------
__global__ void rowmax_kernel() {
    int b  = blockIdx.x >> 6;
    int ib = (blockIdx.x & 63) << 6;
    __shared__ float xs[TI][DD];
    __shared__ float ys[TJ][DD + 1];
    __shared__ float x2s[TI], y2s[TJ];
    __shared__ float red[TI][17];
    int tid = threadIdx.x;
    for (int t = tid; t < TI * DD; t += 256)
        xs[t >> 6][t & 63] = g_xf[(size_t)(b * NN + ib + (t >> 6)) * DD + (t & 63)];
    if (tid < TI) x2s[tid] = g_x2[b * NN + ib + tid];
    int ty = tid >> 4, tx = tid & 15;
    float mymax[4] = {-1e30f, -1e30f, -1e30f, -1e30f};
    for (int jb = 0; jb < NN; jb += TJ) {
        __syncthreads();
        for (int t = tid; t < TJ * DD; t += 256)
            ys[t >> 6][t & 63] = g_yf[(size_t)(b * NN + jb + (t >> 6)) * DD + (t & 63)];
        if (tid < TJ) y2s[tid] = g_y2[b * NN + jb + tid];
        __syncthreads();
        float acc[4][4] = {};
#pragma unroll 16
        for (int k = 0; k < DD; ++k) {
            float a[4], bb[4];
#pragma unroll
            for (int r = 0; r < 4; ++r) a[r] = xs[ty * 4 + r][k];
#pragma unroll
            for (int c = 0; c < 4; ++c) bb[c] = ys[tx * 4 + c][k];
#pragma unroll
            for (int r = 0; r < 4; ++r)
#pragma unroll
                for (int c = 0; c < 4; ++c) acc[r][c] = fmaf(a[r], bb[c], acc[r][c]);
        }
#pragma unroll
        for (int r = 0; r < 4; ++r) {
            float x2 = x2s[ty * 4 + r];
#pragma unroll
            for (int c = 0; c < 4; ++c) {
                float arg = fminf((2.0f * acc[r][c] - x2 - y2s[tx * 4 + c]) * INV_EPS, 0.0f);
                mymax[r] = fmaxf(mymax[r], arg);
            }
        }
    }
    __syncthreads();
#pragma unroll
    for (int r = 0; r < 4; ++r) red[ty * 4 + r][tx] = mymax[r];
    __syncthreads();
    if (tid < TI) {
        float m = -1e30f;
#pragma unroll
        for (int t = 0; t < 16; ++t) m = fmaxf(m, red[tid][t]);
        g_m[b * NN + ib + tid] = m;
    }
}

// ---------------------------------------------------------------------------
// 3) build K~ fp16 (row-major only). grid = B * 64 * 64 = 16384 blocks.
// ---------------------------------------------------------------------------
__global__ void build_kernel() {
    int b   = blockIdx.x >> 12;
    int rem = blockIdx.x & 4095;
    int ib  = (rem >> 6) << 6;
    int jb  = (rem & 63) << 6;
    __shared__ float xs[TI][DD];
    __shared__ float ys[TJ][DD + 1];
    __shared__ float x2s[TI], y2s[TJ], ms[TI];
    int tid = threadIdx.x;
    for (int t = tid; t < TI * DD; t += 256)
        xs[t >> 6][t & 63] = g_xf[(size_t)(b * NN + ib + (t >> 6)) * DD + (t & 63)];
    for (int t = tid; t < TJ * DD; t += 256)
        ys[t >> 6][t & 63] = g_yf[(size_t)(b * NN + jb + (t >> 6)) * DD + (t & 63)];
    if (tid < TI) { x2s[tid] = g_x2[b * NN + ib + tid]; ms[tid] = g_m[b * NN + ib + tid]; }
    if (tid >= 64 && tid < 64 + TJ) y2s[tid - 64] = g_y2[b * NN + jb + tid - 64];
    __syncthreads();
    int ty = tid >> 4, tx = tid & 15;
    float acc[4][4] = {};
#pragma unroll 16
    for (int k = 0; k < DD; ++k) {
        float a[4], bb[4];
#pragma unroll
        for (int r = 0; r < 4; ++r) a[r] = xs[ty * 4 + r][k];
#pragma unroll
        for (int c = 0; c < 4; ++c) bb[c] = ys[tx * 4 + c][k];
#pragma unroll
        for (int r = 0; r < 4; ++r)
#pragma unroll
            for (int c = 0; c < 4; ++c) acc[r][c] = fmaf(a[r], bb[c], acc[r][c]);
    }
#pragma unroll
    for (int r = 0; r < 4; ++r) {
        int i = ty * 4 + r;
        float x2 = x2s[i];
        float m  = ms[i];
        __half hv[4];
#pragma unroll
        for (int c = 0; c < 4; ++c) {
            int j = tx * 4 + c;
            float arg = fminf((2.0f * acc[r][c] - x2 - y2s[j]) * INV_EPS, 0.0f);
            float kv  = __expf(arg - m);
            hv[c] = __float2half_rn(kv);
        }
        size_t rowo = (size_t)(b * NN + ib + i) * NN + jb + tx * 4;
        __half2* dst = reinterpret_cast<__half2*>(&g_K[rowo]);
        dst[0] = __halves2half2(hv[0], hv[1]);
        dst[1] = __halves2half2(hv[2], hv[3]);
    }
}

// ---------------------------------------------------------------------------
// init: wv[0] = N (so v0 = 1/(N+stab) ~= 1/N), wv[1..MAX_ITER] = 0
// ---------------------------------------------------------------------------
__global__ void init_wv_kernel() {
    int i = blockIdx.x * 256 + threadIdx.x;
    const int total = (MAX_ITER + 1) * BATCH * NN;
    if (i < total) g_wv[i] = (i < BATCH * NN) ? (float)NN : 0.0f;
}

// ---------------------------------------------------------------------------
// hinted 32-byte loads (sm_103 ptxas: evict hints require .v4.b64)
// ---------------------------------------------------------------------------
__device__ __forceinline__ ulonglong4 ldg32_pin(const void* p) {
    ulonglong4 r;
    asm("ld.global.L2::evict_last.v4.b64 {%0,%1,%2,%3}, [%4];"
        : "=l"(r.x), "=l"(r.y), "=l"(r.z), "=l"(r.w) : "l"(p));
    return r;
}
__device__ __forceinline__ ulonglong4 ldg32_stream(const void* p) {
    ulonglong4 r;
    asm("ld.global.L2::evict_first.v4.b64 {%0,%1,%2,%3}, [%4];"
        : "=l"(r.x), "=l"(r.y), "=l"(r.z), "=l"(r.w) : "l"(p));
    return r;
}

// ---------------------------------------------------------------------------
// 4) one-pass Sinkhorn iteration. grid = 148 blocks (1/SM), 1024 threads.
//    Row groups of 32:
//      phase1: warp w computes the FULL dot of row grp*32+w with smem v
//              (8 chunks of 32B/lane, rolling 2-deep), u -> smem us[w].
//      barrier
//      phase2: warp w folds rows grp*32..grp*32+R-1 over its 128-column
//              stripe (1 uint2/lane/row, L1/L2 hits) into wa[4] registers.
//      barrier
//    End: atomicAdd wa into wvn (per-iteration pre-zeroed buffer).
// ---------------------------------------------------------------------------
__global__ void __launch_bounds__(1024, 1) iter_kernel(int t) {
    const float* __restrict__ wvp = g_wv + (size_t)t * (BATCH * NN);
    float* __restrict__ wvn = g_wv + (size_t)(t + 1) * (BATCH * NN);
    int b   = blockIdx.x & 3;
    int blk = blockIdx.x >> 2;
    int start = (blk * NN) / NBLK_PER_B;
    int end   = ((blk + 1) * NN) / NBLK_PER_B;
    int nrows = end - start;
    int tid = threadIdx.x;
    int w = tid >> 5, l = tid & 31;
    int c0 = w * 128 + l * 4;      // this thread's fold columns (4)

    __shared__ __align__(16) float sv[NN];   // v for this batch (16 KB)
    __shared__ float us[32];
    __shared__ float ms[128];

    for (int c = tid; c < NN; c += 1024) sv[c] = 1.0f / (wvp[b * NN + c] + STAB);
    for (int r = tid; r < nrows; r += 1024) ms[r] = g_m[b * NN + start + r];

    float wa0 = 0.0f, wa1 = 0.0f, wa2 = 0.0f, wa3 = 0.0f;
    const __half* Kb = g_K + (size_t)b * NN * NN;

    __syncthreads();

    int ngroups = (nrows + 31) >> 5;
    for (int grp = 0; grp < ngroups; ++grp) {
        int r = grp * 32 + w;

        // ---- phase 1: full-row dot by this warp alone ----
        if (r < nrows) {
            const __half* row = Kb + (size_t)(start + r) * NN;
            bool pin = (start + r) < ROWS_PIN;
            ulonglong4 kb[2];
            const void* p0 = (const void*)(row + 0 * 512 + l * 16);
            const void* p1 = (const void*)(row + 1 * 512 + l * 16);
            kb[0] = pin ? ldg32_pin(p0) : ldg32_stream(p0);
            kb[1] = pin ? ldg32_pin(p1) : ldg32_stream(p1);
            float dot = 0.0f;
#pragma unroll
            for (int c = 0; c < 8; ++c) {
                ulonglong4 kk = kb[c & 1];
                if (c < 6) {
                    const void* pn = (const void*)(row + (c + 2) * 512 + l * 16);
                    kb[c & 1] = pin ? ldg32_pin(pn) : ldg32_stream(pn);
                }
                const __half2* h = (const __half2*)&kk;
                const float4* vv = (const float4*)(sv + c * 512 + l * 16);
                float4 v0 = vv[0], v1 = vv[1], v2 = vv[2], v3 = vv[3];
                float2 f0 = __half22float2(h[0]);
                float2 f1 = __half22float2(h[1]);
                float2 f2 = __half22float2(h[2]);
                float2 f3 = __half22float2(h[3]);
                float2 f4 = __half22float2(h[4]);
                float2 f5 = __half22float2(h[5]);
                float2 f6 = __half22float2(h[6]);
                float2 f7 = __half22float2(h[7]);
                dot = fmaf(f0.x, v0.x, dot); dot = fmaf(f0.y, v0.y, dot);
                dot = fmaf(f1.x, v0.z, dot); dot = fmaf(f1.y, v0.w, dot);
                dot = fmaf(f2.x, v1.x, dot); dot = fmaf(f2.y, v1.y, dot);
                dot = fmaf(f3.x, v1.z, dot); dot = fmaf(f3.y, v1.w, dot);
                dot = fmaf(f4.x, v2.x, dot); dot = fmaf(f4.y, v2.y, dot);
                dot = fmaf(f5.x, v2.z, dot); dot = fmaf(f5.y, v2.w, dot);
                dot = fmaf(f6.x, v3.x, dot); dot = fmaf(f6.y, v3.y, dot);
                dot = fmaf(f7.x, v3.z, dot); dot = fmaf(f7.y, v3.w, dot);
            }
#pragma unroll
            for (int o = 16; o > 0; o >>= 1) dot += __shfl_xor_sync(0xffffffffu, dot, o);
            if (l == 0) {
                float em = expf(ms[r]);
                float u  = em / (em * dot + STAB);   // u~ = u * e^m
                us[w] = u;
                g_ut[b * NN + start + r] = u;
            }
        }
        __syncthreads();

        // ---- phase 2: fold group rows over this warp's column stripe ----
        {
            int R = nrows - grp * 32; if (R > 32) R = 32;
            for (int r0 = 0; r0 < R; r0 += 4) {
                int cnt = R - r0; if (cnt > 4) cnt = 4;
                uint2 kc[4];
                float uu[4];
#pragma unroll
                for (int q = 0; q < 4; ++q) {
                    if (q < cnt) {
                        int rr = start + grp * 32 + r0 + q;
                        kc[q] = *(const uint2*)(Kb + (size_t)rr * NN + c0);
                        uu[q] = us[r0 + q];
                    }
                }
#pragma unroll
                for (int q = 0; q < 4; ++q) {
                    if (q < cnt) {
                        float2 f0 = __half22float2(*(const __half2*)&kc[q].x);
                        float2 f1 = __half22float2(*(const __half2*)&kc[q].y);
                        wa0 = fmaf(uu[q], f0.x, wa0);
                        wa1 = fmaf(uu[q], f0.y, wa1);
                        wa2 = fmaf(uu[q], f1.x, wa2);
                        wa3 = fmaf(uu[q], f1.y, wa3);
                    }
                }
            }
        }
        __syncthreads();   // protect us before next group's dots overwrite
    }

    atomicAdd(&wvn[b * NN + c0 + 0], wa0);
    atomicAdd(&wvn[b * NN + c0 + 1], wa1);
    atomicAdd(&wvn[b * NN + c0 + 2], wa2);
    atomicAdd(&wvn[b * NN + c0 + 3], wa3);
}

// ---------------------------------------------------------------------------
// 5) dist partials: sum_ij u~_i * exp(arg_ij - m_i) * v_j * cost_ij
//    v_j = 1/(wv[MAX_ITER][j] + stab)
// ---------------------------------------------------------------------------
__global__ void final_kernel() {
    int b   = blockIdx.x >> 12;
    int rem = blockIdx.x & 4095;
    int ib  = (rem >> 6) << 6;
    int jb  = (rem & 63) << 6;
    __shared__ float xs[TI][DD];
    __shared__ float ys[TJ][DD + 1];
    __shared__ float x2s[TI], y2s[TJ], ms[TI], uts[TI], vs[TJ];
    __shared__ float redsum[256];
    int tid = threadIdx.x;
    for (int t = tid; t < TI * DD; t += 256)
        xs[t >> 6][t & 63] = g_xf[(size_t)(b * NN + ib + (t >> 6)) * DD + (t & 63)];
    for (int t = tid; t < TJ * DD; t += 256)
        ys[t >> 6][t & 63] = g_yf[(size_t)(b * NN + jb + (t >> 6)) * DD + (t & 63)];
    if (tid < TI) {
        x2s[tid] = g_x2[b * NN + ib + tid];
        ms[tid]  = g_m[b * NN + ib + tid];
        uts[tid] = g_ut[b * NN + ib + tid];
    }
    if (tid >= 64 && tid < 64 + TJ) {
        y2s[tid - 64] = g_y2[b * NN + jb + tid - 64];
        vs[tid - 64]  = 1.0f / (g_wv[(size_t)MAX_ITER * (BATCH * NN) + b * NN + jb + tid - 64] + STAB);
    }
    __syncthreads();
    int ty = tid >> 4, tx = tid & 15;
    float acc[4][4] = {};
#pragma unroll 16
    for (int k = 0; k < DD; ++k) {
        float a[4], bb[4];
#pragma unroll
        for (int r = 0; r < 4; ++r) a[r] = xs[ty * 4 + r][k];
#pragma unroll
        for (int c = 0; c < 4; ++c) bb[c] = ys[tx * 4 + c][k];
#pragma unroll
        for (int r = 0; r < 4; ++r)
#pragma unroll
            for (int c = 0; c < 4; ++c) acc[r][c] = fmaf(a[r], bb[c], acc[r][c]);
    }
    float tsum = 0.0f;
#pragma unroll
    for (int r = 0; r < 4; ++r) {
        int i = ty * 4 + r;
        float x2 = x2s[i], m = ms[i], ut = uts[i];
#pragma unroll
        for (int c = 0; c < 4; ++c) {
            int j = tx * 4 + c;
            float cost = fmaxf(x2 + y2s[j] - 2.0f * acc[r][c], 0.0f);
            float kk   = __expf(-cost * INV_EPS - m);
            tsum = fmaf(ut * kk, vs[j] * cost, tsum);
        }
    }
    redsum[tid] = tsum;
    __syncthreads();
#pragma unroll
    for (int o = 128; o > 0; o >>= 1) {
        if (tid < o) redsum[tid] += redsum[tid + o];
        __syncthreads();
    }
    if (tid == 0) g_part[blockIdx.x] = redsum[0];
}

__global__ void reduce_kernel(float* __restrict__ out) {
    __shared__ float sh[256];
    float s = 0.0f;
    for (int t = threadIdx.x; t < BATCH * 64 * 64; t += 256) s += g_part[t];
    sh[threadIdx.x] = s;
    __syncthreads();
#pragma unroll
    for (int o = 128; o > 0; o >>= 1) {
        if (threadIdx.x < o) sh[threadIdx.x] += sh[threadIdx.x + o];
        __syncthreads();
    }
    if (threadIdx.x == 0) out[0] = sh[0];
}

extern "C" void kernel_launch(void* const* d_in, const int* in_sizes, int n_in,
                              void* d_out, int out_size) {
    const float* x = (const float*)d_in[0];
    const float* y = (const float*)d_in[1];
    float* out = (float*)d_out;

    softmax_kernel<<<(2 * BATCH * NN) / 8, 256>>>(x, y);
    rowmax_kernel<<<BATCH * (NN / 64), 256>>>();
    build_kernel<<<BATCH * 64 * 64, 256>>>();
    {
        const int total = (MAX_ITER + 1) * BATCH * NN;
        init_wv_kernel<<<(total + 255) / 256, 256>>>();
    }
    for (int it = 0; it < MAX_ITER; ++it) {
        iter_kernel<<<4 * NBLK_PER_B, 1024>>>(it);
    }
    final_kernel<<<BATCH * 64 * 64, 256>>>();
    reduce_kernel<<<1, 256>>>(out);
}